// round 5
// baseline (speedup 1.0000x reference)
#include <cuda_runtime.h>
#include <cstdint>

#define B_  2
#define C_  256
#define KCOL 2304   // C_ * 9

// ---------------- scratch (device globals: allocation-free) ----------------
// g_corr doubles as the split-K partial buffer after the offset kernel is done.
__device__ float g_corr[2 * 289 * 64 * 64];   // 2.37M floats
__device__ float g_off [2 *  72 * 64 * 64];   // offsets
__device__ float g_col [2 * KCOL * 64 * 64];  // im2col buffer (~76 MB)

// ---------------- 1. windowed pointwise correlation ----------------
// Thread tile: 8 pixels x 4 ox-shifts (one dy). f1 loaded as 2x float4 and
// reused across 4 shifts; f2 window (span = 8+3*stride) reused across the
// 8x4 outputs -> ~2.9x fewer warp-LDGs than naive.
template<int STRIDE>
__global__ void __launch_bounds__(256)
corr_kernel2(const float* __restrict__ x, int H, int W,
             int disp, int K2, int D, int OXC, int total)
{
    constexpr int PX = 8, KX = 4;
    constexpr int SPAN = PX + (KX - 1) * STRIDE;

    const int idx = blockIdx.x * 256 + threadIdx.x;
    if (idx >= total) return;
    const int HW = H * W;
    const int PB = HW / PX;

    int t = idx;
    const int pb  = t % PB;  t /= PB;
    const int oxc = t % OXC; t /= OXC;
    const int dy  = t % D;   t /= D;
    const int b   = t;

    const int p0 = pb * PX;
    const int h  = p0 / W, w0 = p0 % W;
    const int yy = h + (dy - disp) * STRIDE;
    const int kx0 = oxc * KX;
    const int xbase = w0 + (kx0 - disp) * STRIDE;

    float acc[KX][PX] = {};

    if (yy >= 0 && yy < H) {
        const float* f1p = x + ((size_t)(2 + b) * C_) * HW + p0;   // x[1][b]
        const float* f2p = x + ((size_t)b * C_) * HW + (size_t)yy * W;
        for (int c = 0; c < C_; c++) {
            const float4 a0 = *(const float4*)f1p;
            const float4 a1 = *(const float4*)(f1p + 4);
            const float a[PX] = {a0.x, a0.y, a0.z, a0.w, a1.x, a1.y, a1.z, a1.w};
            float fv[SPAN];
#pragma unroll
            for (int s = 0; s < SPAN; s++) {
                const int col = xbase + s;
                fv[s] = ((unsigned)col < (unsigned)W) ? __ldg(f2p + col) : 0.f;
            }
#pragma unroll
            for (int j = 0; j < KX; j++)
#pragma unroll
                for (int i = 0; i < PX; i++)
                    acc[j][i] = fmaf(a[i], fv[j * STRIDE + i], acc[j][i]);
            f1p += HW; f2p += HW;
        }
    }

    const float sc = 1.f / C_;
#pragma unroll
    for (int j = 0; j < KX; j++) {
        const int kx = kx0 + j;
        if (kx < D) {
            float* op = g_corr + ((size_t)(b * K2) + dy * D + kx) * HW + p0;
            float4 v0 = {acc[j][0] * sc, acc[j][1] * sc, acc[j][2] * sc, acc[j][3] * sc};
            float4 v1 = {acc[j][4] * sc, acc[j][5] * sc, acc[j][6] * sc, acc[j][7] * sc};
            *(float4*)op = v0;
            *(float4*)(op + 4) = v1;
        }
    }
}

// ---------------- 2. offset = w_off[72,K2] @ corr[K2,HW] ----------------
// Block owns 8 output channels; w[8][K2] staged in smem -> 1 corr LDG per k.
__global__ void __launch_bounds__(256)
offset_kernel2(const float* __restrict__ w_off, int HW, int K2)
{
    __shared__ float ws[8 * 289];
    const int oc = blockIdx.y;        // 0..8  -> channels oc*8 .. oc*8+7
    const int b  = blockIdx.z;
    const int tid = threadIdx.x;

    for (int i = tid; i < 8 * K2; i += 256)
        ws[i] = w_off[(size_t)(oc * 8 + i / K2) * K2 + (i % K2)];
    __syncthreads();

    const int p = blockIdx.x * 256 + tid;
    if (p >= HW) return;

    const float* cb = g_corr + (size_t)b * K2 * HW + p;
    float acc[8] = {};
    for (int k = 0; k < K2; k++) {
        const float v = cb[(size_t)k * HW];
#pragma unroll
        for (int o = 0; o < 8; o++)
            acc[o] = fmaf(ws[o * K2 + k], v, acc[o]);
    }
#pragma unroll
    for (int o = 0; o < 8; o++)
        g_off[((size_t)(b * 72 + oc * 8 + o)) * HW + p] = acc[o];
}

// ---------------- 3. bilinear im2col (4 channels per thread) ----------------
// Offsets + bilinear weights depend only on (g,k,p): amortized over 4 channels.
__global__ void im2col_kernel2(const float* __restrict__ x, int H, int W)
{
    const int HW = H * W;
    const size_t total = (size_t)B_ * 4 * 16 * 9 * HW;
    size_t idx = (size_t)blockIdx.x * blockDim.x + threadIdx.x;
    if (idx >= total) return;

    const int p = (int)(idx % HW);
    size_t r = idx / HW;
    const int k = (int)(r % 9);  r /= 9;
    const int q = (int)(r % 16); r /= 16;
    const int g = (int)(r % 4);
    const int n = (int)(r / 4);
    const int c0 = g * 64 + q * 4;
    const int h = p / W, w = p % W;

    const float* ob = g_off + ((size_t)(n * 72 + (g * 9 + k) * 2)) * HW + p;
    const float oy = ob[0];
    const float ox = ob[HW];

    const float y  = (float)(k / 3 - 1 + h) + oy;
    const float xf = (float)(k % 3 - 1 + w) + ox;
    const float y0f = floorf(y), x0f = floorf(xf);
    const float wy = y - y0f, wx = xf - x0f;
    const int y0 = (int)y0f, x0 = (int)x0f;

    const bool yv0 = (y0 >= 0)     & (y0 < H);
    const bool yv1 = (y0 + 1 >= 0) & (y0 + 1 < H);
    const bool xv0 = (x0 >= 0)     & (x0 < W);
    const bool xv1 = (x0 + 1 >= 0) & (x0 + 1 < W);
    const float w00 = (yv0 && xv0) ? (1.f - wy) * (1.f - wx) : 0.f;
    const float w01 = (yv0 && xv1) ? (1.f - wy) * wx         : 0.f;
    const float w10 = (yv1 && xv0) ? wy * (1.f - wx)         : 0.f;
    const float w11 = (yv1 && xv1) ? wy * wx                 : 0.f;
    const int i00 = yv0 && xv0 ? y0 * W + x0           : 0;
    const int i01 = yv0 && xv1 ? y0 * W + x0 + 1       : 0;
    const int i10 = yv1 && xv0 ? (y0 + 1) * W + x0     : 0;
    const int i11 = yv1 && xv1 ? (y0 + 1) * W + x0 + 1 : 0;

#pragma unroll
    for (int cl = 0; cl < 4; cl++) {
        const int c = c0 + cl;
        const float* img = x + ((size_t)(2 + n) * C_ + c) * HW;   // x[1][n]
        const float val = img[i00] * w00 + img[i01] * w01
                        + img[i10] * w10 + img[i11] * w11;
        g_col[((size_t)n * KCOL + (size_t)(c * 9 + k)) * HW + p] = val;
    }
}

// ---------------- 4a. direct GEMM + ReLU (level 0: full K per CTA) ----------
__global__ void __launch_bounds__(256)
gemm_relu_kernel(const float* __restrict__ A, float* __restrict__ out_base, int N)
{
    const int n_idx = blockIdx.z;
    const float* __restrict__ Bm = g_col + (size_t)n_idx * KCOL * N;
    float* __restrict__ Cm = out_base + ((size_t)(2 + n_idx)) * C_ * N;

    const int bm = blockIdx.y * 128;
    const int bn = blockIdx.x * 64;

    __shared__ float As[16][129];
    __shared__ float Bs[16][64];

    const int tid = threadIdx.x;
    const int tx = tid & 15, ty = tid >> 4;
    const int ar = tid >> 1, ac = (tid & 1) * 8;
    const int br = tid >> 4, bc = (tid & 15) * 4;

    const float* aPtr = A  + (size_t)(bm + ar) * KCOL + ac;
    const float* bPtr = Bm + (size_t)br * N + bn + bc;

    float acc[8][4] = {};
    float4 pa0 = *(const float4*)(aPtr);
    float4 pa1 = *(const float4*)(aPtr + 4);
    float4 pb  = *(const float4*)(bPtr);

    for (int k0 = 0; k0 < KCOL; k0 += 16) {
        As[ac + 0][ar] = pa0.x; As[ac + 1][ar] = pa0.y;
        As[ac + 2][ar] = pa0.z; As[ac + 3][ar] = pa0.w;
        As[ac + 4][ar] = pa1.x; As[ac + 5][ar] = pa1.y;
        As[ac + 6][ar] = pa1.z; As[ac + 7][ar] = pa1.w;
        *(float4*)&Bs[br][bc] = pb;
        __syncthreads();
        if (k0 + 16 < KCOL) {
            pa0 = *(const float4*)(aPtr + k0 + 16);
            pa1 = *(const float4*)(aPtr + k0 + 20);
            pb  = *(const float4*)(bPtr + (size_t)(k0 + 16) * N);
        }
#pragma unroll
        for (int kk = 0; kk < 16; kk++) {
            float a[8], b[4];
#pragma unroll
            for (int i = 0; i < 8; i++) a[i] = As[kk][ty * 8 + i];
#pragma unroll
            for (int j = 0; j < 4; j++) b[j] = Bs[kk][tx * 4 + j];
#pragma unroll
            for (int i = 0; i < 8; i++)
#pragma unroll
                for (int j = 0; j < 4; j++)
                    acc[i][j] = fmaf(a[i], b[j], acc[i][j]);
        }
        __syncthreads();
    }
#pragma unroll
    for (int i = 0; i < 8; i++) {
        const int m = bm + ty * 8 + i;
        float4 v;
        v.x = fmaxf(acc[i][0], 0.f); v.y = fmaxf(acc[i][1], 0.f);
        v.z = fmaxf(acc[i][2], 0.f); v.w = fmaxf(acc[i][3], 0.f);
        *(float4*)&Cm[(size_t)m * N + bn + tx * 4] = v;
    }
}

// ---------------- 4b. split-K GEMM (levels 1-3): partials into g_corr -------
__global__ void __launch_bounds__(256)
gemm_splitk_kernel(const float* __restrict__ A, int N, int KS)
{
    const int z = blockIdx.z;
    const int n_idx = z % B_;
    const int s     = z / B_;
    const float* __restrict__ Bm = g_col + (size_t)n_idx * KCOL * N;
    float* __restrict__ Pm = g_corr + ((size_t)(s * B_ + n_idx)) * C_ * N;

    const int ks = s * KS;
    const int bm = blockIdx.y * 128;
    const int bn = blockIdx.x * 64;

    __shared__ float As[16][129];
    __shared__ float Bs[16][64];

    const int tid = threadIdx.x;
    const int tx = tid & 15, ty = tid >> 4;
    const int ar = tid >> 1, ac = (tid & 1) * 8;
    const int br = tid >> 4, bc = (tid & 15) * 4;

    const float* aPtr = A  + (size_t)(bm + ar) * KCOL + ks + ac;
    const float* bPtr = Bm + (size_t)(ks + br) * N + bn + bc;

    float acc[8][4] = {};
    float4 pa0 = *(const float4*)(aPtr);
    float4 pa1 = *(const float4*)(aPtr + 4);
    float4 pb  = *(const float4*)(bPtr);

    for (int k0 = 0; k0 < KS; k0 += 16) {
        As[ac + 0][ar] = pa0.x; As[ac + 1][ar] = pa0.y;
        As[ac + 2][ar] = pa0.z; As[ac + 3][ar] = pa0.w;
        As[ac + 4][ar] = pa1.x; As[ac + 5][ar] = pa1.y;
        As[ac + 6][ar] = pa1.z; As[ac + 7][ar] = pa1.w;
        *(float4*)&Bs[br][bc] = pb;
        __syncthreads();
        if (k0 + 16 < KS) {
            pa0 = *(const float4*)(aPtr + k0 + 16);
            pa1 = *(const float4*)(aPtr + k0 + 20);
            pb  = *(const float4*)(bPtr + (size_t)(k0 + 16) * N);
        }
#pragma unroll
        for (int kk = 0; kk < 16; kk++) {
            float a[8], b[4];
#pragma unroll
            for (int i = 0; i < 8; i++) a[i] = As[kk][ty * 8 + i];
#pragma unroll
            for (int j = 0; j < 4; j++) b[j] = Bs[kk][tx * 4 + j];
#pragma unroll
            for (int i = 0; i < 8; i++)
#pragma unroll
                for (int j = 0; j < 4; j++)
                    acc[i][j] = fmaf(a[i], b[j], acc[i][j]);
        }
        __syncthreads();
    }
#pragma unroll
    for (int i = 0; i < 8; i++) {
        const int m = bm + ty * 8 + i;
        float4 v = {acc[i][0], acc[i][1], acc[i][2], acc[i][3]};
        *(float4*)&Pm[(size_t)m * N + bn + tx * 4] = v;
    }
}

// ---------------- 4c. split-K reduce + ReLU --------------------------------
__global__ void reduce_relu_kernel(float* __restrict__ dst, int S, int total4)
{
    const int i = blockIdx.x * 256 + threadIdx.x;
    if (i >= total4) return;
    const float4* src = (const float4*)g_corr;
    const size_t stride4 = (size_t)total4;   // B*C*HW/4 per slice
    float4 a = {0.f, 0.f, 0.f, 0.f};
    for (int s = 0; s < S; s++) {
        const float4 v = src[(size_t)s * stride4 + i];
        a.x += v.x; a.y += v.y; a.z += v.z; a.w += v.w;
    }
    a.x = fmaxf(a.x, 0.f); a.y = fmaxf(a.y, 0.f);
    a.z = fmaxf(a.z, 0.f); a.w = fmaxf(a.w, 0.f);
    ((float4*)dst)[i] = a;
}

// ---------------- host orchestration ----------------
extern "C" void kernel_launch(void* const* d_in, const int* in_sizes, int n_in,
                              void* d_out, int out_size)
{
    static const int Hs[4]      = {64, 32, 16, 8};
    static const int disps[4]   = {8, 8, 4, 2};
    static const int strides[4] = {2, 1, 1, 1};
    static const int splits[4]  = {1, 4, 16, 36};   // K-split per level

    const bool interleaved = (n_in >= 6) && (in_sizes[5] > 100000);

    float* out = (float*)d_out;
    size_t out_off = 0;

    for (int l = 0; l < 4; l++) {
        const int H = Hs[l], W = H, HW = H * W;
        const int disp = disps[l], stride = strides[l];
        const int D = 2 * disp + 1;
        const int K2 = D * D;
        const int OXC = (D + 3) / 4;
        const float* x       = (const float*)d_in[l];
        const float* w_off   = (const float*)d_in[interleaved ? (4 + 2 * l) : (4 + l)];
        const float* w_adapt = (const float*)d_in[interleaved ? (5 + 2 * l) : (8 + l)];
        const size_t CHW = (size_t)C_ * HW;

        // passthrough: out[0:2] = x[0]
        cudaMemcpyAsync(out + out_off, x, (size_t)B_ * CHW * sizeof(float),
                        cudaMemcpyDeviceToDevice);

        // correlation
        const int ctotal = B_ * D * OXC * (HW / 8);
        const int cblocks = (ctotal + 255) / 256;
        if (stride == 2)
            corr_kernel2<2><<<cblocks, 256>>>(x, H, W, disp, K2, D, OXC, ctotal);
        else
            corr_kernel2<1><<<cblocks, 256>>>(x, H, W, disp, K2, D, OXC, ctotal);

        // offsets
        dim3 ogrid((HW + 255) / 256, 9, B_);
        offset_kernel2<<<ogrid, 256>>>(w_off, HW, K2);

        // im2col
        const size_t itotal = (size_t)B_ * 4 * 16 * 9 * HW;
        im2col_kernel2<<<(unsigned)((itotal + 255) / 256), 256>>>(x, H, W);

        // GEMM + ReLU
        if (splits[l] == 1) {
            dim3 ggrid(HW / 64, C_ / 128, B_);
            gemm_relu_kernel<<<ggrid, 256>>>(w_adapt, out + out_off, HW);
        } else {
            const int S = splits[l];
            const int KS = KCOL / S;
            dim3 ggrid(HW / 64, C_ / 128, B_ * S);
            gemm_splitk_kernel<<<ggrid, 256>>>(w_adapt, HW, KS);
            const int total4 = (int)((size_t)B_ * C_ * HW / 4);
            reduce_relu_kernel<<<(total4 + 255) / 256, 256>>>(
                out + out_off + (size_t)B_ * CHW, S, total4);
        }

        out_off += (size_t)4 * CHW;   // [x0 (2 batches), feat (2 batches)]
    }
}

// round 13
// speedup vs baseline: 1.7300x; 1.7300x over previous
#include <cuda_runtime.h>
#include <cstdint>

#define B_  2
#define C_  256
#define KCOL 2304   // C_ * 9

// ---------------- scratch (device globals: allocation-free) ----------------
// g_corr doubles as the split-K partial buffer after the offset kernel is done.
// 16B alignment: these bases are accessed via float4/ulonglong2 (128-bit) ops.
__device__ __align__(16) float g_corr[2 * 289 * 64 * 64];   // 2.37M floats
__device__ __align__(16) float g_off [2 *  72 * 64 * 64];   // offsets
__device__ __align__(16) float g_col [2 * KCOL * 64 * 64];  // im2col (~76 MB)

// ---------------- packed f32x2 helpers ----------------
__device__ __forceinline__ unsigned long long fma2(unsigned long long a,
                                                   unsigned long long b,
                                                   unsigned long long c) {
    unsigned long long d;
    asm("fma.rn.f32x2 %0, %1, %2, %3;" : "=l"(d) : "l"(a), "l"(b), "l"(c));
    return d;
}
__device__ __forceinline__ unsigned long long pack2(float lo, float hi) {
    unsigned long long d;
    asm("mov.b64 %0, {%1, %2};" : "=l"(d) : "f"(lo), "f"(hi));
    return d;
}
__device__ __forceinline__ float2 unpack2(unsigned long long v) {
    float2 r;
    asm("mov.b64 {%0, %1}, %2;" : "=f"(r.x), "=f"(r.y) : "l"(v));
    return r;
}

// ---------------- 1. windowed pointwise correlation (naive, coalesced) -----
// corr[b,k,h,w] = (1/C) * sum_c x1[b,c,h,w] * x0[b,c,h+oy,w+ox], zero OOB.
// warp = 32 consecutive pixels, same shift -> both LDGs 1-line coalesced.
__global__ void corr_kernel(const float* __restrict__ x,
                            int H, int W, int disp, int stride, int K2)
{
    const int HW  = H * W;
    const int CHW = C_ * HW;
    const int b = blockIdx.z;
    const int k = blockIdx.y * 8 + (threadIdx.x >> 5);
    const int p = blockIdx.x * 32 + (threadIdx.x & 31);
    if (k >= K2 || p >= HW) return;

    const int D  = 2 * disp + 1;
    const int oy = (k / D - disp) * stride;
    const int ox = (k % D - disp) * stride;
    const int h = p / W, w = p % W;
    const int yy = h + oy, xx = w + ox;

    float out = 0.f;
    if (yy >= 0 && yy < H && xx >= 0 && xx < W) {
        const float* f1 = x + (size_t)(2 + b) * CHW + p;        // x[1][b]
        const float* f2 = x + (size_t)b * CHW + yy * W + xx;    // x[0][b] shifted
        float acc = 0.f;
#pragma unroll 8
        for (int c = 0; c < C_; c++)
            acc = fmaf(f1[(size_t)c * HW], f2[(size_t)c * HW], acc);
        out = acc * (1.f / C_);
    }
    g_corr[((size_t)(b * K2 + k)) * HW + p] = out;
}

// ---------------- 2. offset = w_off[72,K2] @ corr[K2,HW] ----------------
// Block owns 8 output channels; w[8][K2] staged in smem -> 1 corr LDG per k.
__global__ void __launch_bounds__(256)
offset_kernel2(const float* __restrict__ w_off, int HW, int K2)
{
    __shared__ float ws[8 * 289];
    const int oc = blockIdx.y;        // 0..8  -> channels oc*8 .. oc*8+7
    const int b  = blockIdx.z;
    const int tid = threadIdx.x;

    for (int i = tid; i < 8 * K2; i += 256)
        ws[i] = w_off[(size_t)(oc * 8 + i / K2) * K2 + (i % K2)];
    __syncthreads();

    const int p = blockIdx.x * 256 + tid;
    if (p >= HW) return;

    const float* cb = g_corr + (size_t)b * K2 * HW + p;
    float acc[8] = {};
    for (int k = 0; k < K2; k++) {
        const float v = cb[(size_t)k * HW];
#pragma unroll
        for (int o = 0; o < 8; o++)
            acc[o] = fmaf(ws[o * K2 + k], v, acc[o]);
    }
#pragma unroll
    for (int o = 0; o < 8; o++)
        g_off[((size_t)(b * 72 + oc * 8 + o)) * HW + p] = acc[o];
}

// ---------------- 3. bilinear im2col (4 channels per thread) ----------------
__global__ void im2col_kernel2(const float* __restrict__ x, int H, int W)
{
    const int HW = H * W;
    const size_t total = (size_t)B_ * 4 * 16 * 9 * HW;
    size_t idx = (size_t)blockIdx.x * blockDim.x + threadIdx.x;
    if (idx >= total) return;

    const int p = (int)(idx % HW);
    size_t r = idx / HW;
    const int k = (int)(r % 9);  r /= 9;
    const int q = (int)(r % 16); r /= 16;
    const int g = (int)(r % 4);
    const int n = (int)(r / 4);
    const int c0 = g * 64 + q * 4;
    const int h = p / W, w = p % W;

    const float* ob = g_off + ((size_t)(n * 72 + (g * 9 + k) * 2)) * HW + p;
    const float oy = ob[0];
    const float ox = ob[HW];

    const float y  = (float)(k / 3 - 1 + h) + oy;
    const float xf = (float)(k % 3 - 1 + w) + ox;
    const float y0f = floorf(y), x0f = floorf(xf);
    const float wy = y - y0f, wx = xf - x0f;
    const int y0 = (int)y0f, x0 = (int)x0f;

    const bool yv0 = (y0 >= 0)     & (y0 < H);
    const bool yv1 = (y0 + 1 >= 0) & (y0 + 1 < H);
    const bool xv0 = (x0 >= 0)     & (x0 < W);
    const bool xv1 = (x0 + 1 >= 0) & (x0 + 1 < W);
    const float w00 = (yv0 && xv0) ? (1.f - wy) * (1.f - wx) : 0.f;
    const float w01 = (yv0 && xv1) ? (1.f - wy) * wx         : 0.f;
    const float w10 = (yv1 && xv0) ? wy * (1.f - wx)         : 0.f;
    const float w11 = (yv1 && xv1) ? wy * wx                 : 0.f;
    const int i00 = yv0 && xv0 ? y0 * W + x0           : 0;
    const int i01 = yv0 && xv1 ? y0 * W + x0 + 1       : 0;
    const int i10 = yv1 && xv0 ? (y0 + 1) * W + x0     : 0;
    const int i11 = yv1 && xv1 ? (y0 + 1) * W + x0 + 1 : 0;

#pragma unroll
    for (int cl = 0; cl < 4; cl++) {
        const int c = c0 + cl;
        const float* img = x + ((size_t)(2 + n) * C_ + c) * HW;   // x[1][n]
        const float val = img[i00] * w00 + img[i01] * w01
                        + img[i10] * w10 + img[i11] * w11;
        g_col[((size_t)n * KCOL + (size_t)(c * 9 + k)) * HW + p] = val;
    }
}

// ---------------- 4a. direct GEMM + ReLU (level 0) ----------
// BM=128, BN=64, BK=16, 256 threads, 8x4 per-thread tile, f32x2 packed FFMA.
__global__ void __launch_bounds__(256)
gemm_relu_kernel(const float* __restrict__ A, float* __restrict__ out_base, int N)
{
    const int n_idx = blockIdx.z;
    const float* __restrict__ Bm = g_col + (size_t)n_idx * KCOL * N;
    float* __restrict__ Cm = out_base + ((size_t)(2 + n_idx)) * C_ * N;

    const int bm = blockIdx.y * 128;
    const int bn = blockIdx.x * 64;

    __shared__ __align__(16) float As[16][132];   // 528B rows: 16B-aligned
    __shared__ __align__(16) float Bs[16][64];

    const int tid = threadIdx.x;
    const int tx = tid & 15, ty = tid >> 4;
    const int ar = tid >> 1, ac = (tid & 1) * 8;
    const int br = tid >> 4, bc = (tid & 15) * 4;

    const float* aPtr = A  + (size_t)(bm + ar) * KCOL + ac;
    const float* bPtr = Bm + (size_t)br * N + bn + bc;

    unsigned long long acc2[4][4] = {};
    float4 pa0 = *(const float4*)(aPtr);
    float4 pa1 = *(const float4*)(aPtr + 4);
    float4 pb  = *(const float4*)(bPtr);

    for (int k0 = 0; k0 < KCOL; k0 += 16) {
        As[ac + 0][ar] = pa0.x; As[ac + 1][ar] = pa0.y;
        As[ac + 2][ar] = pa0.z; As[ac + 3][ar] = pa0.w;
        As[ac + 4][ar] = pa1.x; As[ac + 5][ar] = pa1.y;
        As[ac + 6][ar] = pa1.z; As[ac + 7][ar] = pa1.w;
        *(float4*)&Bs[br][bc] = pb;
        __syncthreads();
        if (k0 + 16 < KCOL) {
            pa0 = *(const float4*)(aPtr + k0 + 16);
            pa1 = *(const float4*)(aPtr + k0 + 20);
            pb  = *(const float4*)(bPtr + (size_t)(k0 + 16) * N);
        }
#pragma unroll
        for (int kk = 0; kk < 16; kk++) {
            const ulonglong2 av0 = *(const ulonglong2*)&As[kk][ty * 8];
            const ulonglong2 av1 = *(const ulonglong2*)&As[kk][ty * 8 + 4];
            const unsigned long long am[4] = {av0.x, av0.y, av1.x, av1.y};
            const float4 b4 = *(const float4*)&Bs[kk][tx * 4];
            const unsigned long long bb[4] = {
                pack2(b4.x, b4.x), pack2(b4.y, b4.y),
                pack2(b4.z, b4.z), pack2(b4.w, b4.w)};
#pragma unroll
            for (int i2 = 0; i2 < 4; i2++)
#pragma unroll
                for (int j = 0; j < 4; j++)
                    acc2[i2][j] = fma2(am[i2], bb[j], acc2[i2][j]);
        }
        __syncthreads();
    }

#pragma unroll
    for (int i2 = 0; i2 < 4; i2++) {
        const int m0 = bm + ty * 8 + 2 * i2;
        const float2 c0 = unpack2(acc2[i2][0]);
        const float2 c1 = unpack2(acc2[i2][1]);
        const float2 c2 = unpack2(acc2[i2][2]);
        const float2 c3 = unpack2(acc2[i2][3]);
        float4 v0 = {fmaxf(c0.x, 0.f), fmaxf(c1.x, 0.f),
                     fmaxf(c2.x, 0.f), fmaxf(c3.x, 0.f)};
        float4 v1 = {fmaxf(c0.y, 0.f), fmaxf(c1.y, 0.f),
                     fmaxf(c2.y, 0.f), fmaxf(c3.y, 0.f)};
        *(float4*)&Cm[(size_t)m0 * N + bn + tx * 4]       = v0;
        *(float4*)&Cm[(size_t)(m0 + 1) * N + bn + tx * 4] = v1;
    }
}

// ---------------- 4b. split-K GEMM (levels 1-3): partials into g_corr -------
__global__ void __launch_bounds__(256)
gemm_splitk_kernel(const float* __restrict__ A, int N, int KS)
{
    const int z = blockIdx.z;
    const int n_idx = z % B_;
    const int s     = z / B_;
    const float* __restrict__ Bm = g_col + (size_t)n_idx * KCOL * N;
    float* __restrict__ Pm = g_corr + ((size_t)(s * B_ + n_idx)) * C_ * N;

    const int ks = s * KS;
    const int bm = blockIdx.y * 128;
    const int bn = blockIdx.x * 64;

    __shared__ __align__(16) float As[16][132];
    __shared__ __align__(16) float Bs[16][64];

    const int tid = threadIdx.x;
    const int tx = tid & 15, ty = tid >> 4;
    const int ar = tid >> 1, ac = (tid & 1) * 8;
    const int br = tid >> 4, bc = (tid & 15) * 4;

    const float* aPtr = A  + (size_t)(bm + ar) * KCOL + ks + ac;
    const float* bPtr = Bm + (size_t)(ks + br) * N + bn + bc;

    unsigned long long acc2[4][4] = {};
    float4 pa0 = *(const float4*)(aPtr);
    float4 pa1 = *(const float4*)(aPtr + 4);
    float4 pb  = *(const float4*)(bPtr);

    for (int k0 = 0; k0 < KS; k0 += 16) {
        As[ac + 0][ar] = pa0.x; As[ac + 1][ar] = pa0.y;
        As[ac + 2][ar] = pa0.z; As[ac + 3][ar] = pa0.w;
        As[ac + 4][ar] = pa1.x; As[ac + 5][ar] = pa1.y;
        As[ac + 6][ar] = pa1.z; As[ac + 7][ar] = pa1.w;
        *(float4*)&Bs[br][bc] = pb;
        __syncthreads();
        if (k0 + 16 < KS) {
            pa0 = *(const float4*)(aPtr + k0 + 16);
            pa1 = *(const float4*)(aPtr + k0 + 20);
            pb  = *(const float4*)(bPtr + (size_t)(k0 + 16) * N);
        }
#pragma unroll
        for (int kk = 0; kk < 16; kk++) {
            const ulonglong2 av0 = *(const ulonglong2*)&As[kk][ty * 8];
            const ulonglong2 av1 = *(const ulonglong2*)&As[kk][ty * 8 + 4];
            const unsigned long long am[4] = {av0.x, av0.y, av1.x, av1.y};
            const float4 b4 = *(const float4*)&Bs[kk][tx * 4];
            const unsigned long long bb[4] = {
                pack2(b4.x, b4.x), pack2(b4.y, b4.y),
                pack2(b4.z, b4.z), pack2(b4.w, b4.w)};
#pragma unroll
            for (int i2 = 0; i2 < 4; i2++)
#pragma unroll
                for (int j = 0; j < 4; j++)
                    acc2[i2][j] = fma2(am[i2], bb[j], acc2[i2][j]);
        }
        __syncthreads();
    }

#pragma unroll
    for (int i2 = 0; i2 < 4; i2++) {
        const int m0 = bm + ty * 8 + 2 * i2;
        const float2 c0 = unpack2(acc2[i2][0]);
        const float2 c1 = unpack2(acc2[i2][1]);
        const float2 c2 = unpack2(acc2[i2][2]);
        const float2 c3 = unpack2(acc2[i2][3]);
        float4 v0 = {c0.x, c1.x, c2.x, c3.x};
        float4 v1 = {c0.y, c1.y, c2.y, c3.y};
        *(float4*)&Pm[(size_t)m0 * N + bn + tx * 4]       = v0;
        *(float4*)&Pm[(size_t)(m0 + 1) * N + bn + tx * 4] = v1;
    }
}

// ---------------- 4c. split-K reduce + ReLU --------------------------------
__global__ void reduce_relu_kernel(float* __restrict__ dst, int S, int total4)
{
    const int i = blockIdx.x * 256 + threadIdx.x;
    if (i >= total4) return;
    const float4* src = (const float4*)g_corr;
    const size_t stride4 = (size_t)total4;   // B*C*HW/4 per slice
    float4 a = {0.f, 0.f, 0.f, 0.f};
    for (int s = 0; s < S; s++) {
        const float4 v = src[(size_t)s * stride4 + i];
        a.x += v.x; a.y += v.y; a.z += v.z; a.w += v.w;
    }
    a.x = fmaxf(a.x, 0.f); a.y = fmaxf(a.y, 0.f);
    a.z = fmaxf(a.z, 0.f); a.w = fmaxf(a.w, 0.f);
    ((float4*)dst)[i] = a;
}

// ---------------- host orchestration ----------------
extern "C" void kernel_launch(void* const* d_in, const int* in_sizes, int n_in,
                              void* d_out, int out_size)
{
    static const int Hs[4]      = {64, 32, 16, 8};
    static const int disps[4]   = {8, 8, 4, 2};
    static const int strides[4] = {2, 1, 1, 1};
    static const int splits[4]  = {1, 4, 16, 36};   // K-split per level

    const bool interleaved = (n_in >= 6) && (in_sizes[5] > 100000);

    float* out = (float*)d_out;
    size_t out_off = 0;

    for (int l = 0; l < 4; l++) {
        const int H = Hs[l], W = H, HW = H * W;
        const int disp = disps[l], stride = strides[l];
        const int D = 2 * disp + 1;
        const int K2 = D * D;
        const float* x       = (const float*)d_in[l];
        const float* w_off   = (const float*)d_in[interleaved ? (4 + 2 * l) : (4 + l)];
        const float* w_adapt = (const float*)d_in[interleaved ? (5 + 2 * l) : (8 + l)];
        const size_t CHW = (size_t)C_ * HW;

        // passthrough: out[0:2] = x[0]
        cudaMemcpyAsync(out + out_off, x, (size_t)B_ * CHW * sizeof(float),
                        cudaMemcpyDeviceToDevice);

        // correlation (naive coalesced)
        dim3 cgrid((HW + 31) / 32, (K2 + 7) / 8, B_);
        corr_kernel<<<cgrid, 256>>>(x, H, W, disp, stride, K2);

        // offsets
        dim3 ogrid((HW + 255) / 256, 9, B_);
        offset_kernel2<<<ogrid, 256>>>(w_off, HW, K2);

        // im2col
        const size_t itotal = (size_t)B_ * 4 * 16 * 9 * HW;
        im2col_kernel2<<<(unsigned)((itotal + 255) / 256), 256>>>(x, H, W);

        // GEMM + ReLU
        if (splits[l] == 1) {
            dim3 ggrid(HW / 64, C_ / 128, B_);
            gemm_relu_kernel<<<ggrid, 256>>>(w_adapt, out + out_off, HW);
        } else {
            const int S = splits[l];
            const int KS = KCOL / S;
            dim3 ggrid(HW / 64, C_ / 128, B_ * S);
            gemm_splitk_kernel<<<ggrid, 256>>>(w_adapt, HW, KS);
            const int total4 = (int)((size_t)B_ * C_ * HW / 4);
            reduce_relu_kernel<<<(total4 + 255) / 256, 256>>>(
                out + out_off + (size_t)B_ * CHW, S, total4);
        }

        out_off += (size_t)4 * CHW;   // [x0 (2 batches), feat (2 batches)]
    }
}